// round 5
// baseline (speedup 1.0000x reference)
#include <cuda_runtime.h>
#include <math.h>
#include <stdint.h>

#define SS 64
#define NN 256
#define CC 3
#define BB 64
#define LL 2048
#define WW (LL - SS + 1)   /* 1985 */
#define WPAD 2048
#define NT 32              /* shapelets per block */
#define NPAIR 16
#define SHP_STRIDE 66      /* float2 row stride: 528B, 16B-aligned, conflict-free */
#define WG 16              /* w-groups (threads dim) */
#define WPT 8              /* w per thread per chunk */
#define WSLICE 8           /* w slices (blockIdx.z) */
#define WPB 256            /* w per block */
#define CHUNKS 2           /* 2 x 128 w per block */
#define XS 320             /* staged x values per channel */
#define THREADS 256

__device__ float g_winsq[BB * CC * WPAD];

// ---------- packed f32x2 helpers (sm_103a fma pipe, 2x fp32 throughput) ----------
__device__ __forceinline__ unsigned long long pack2(float v) {
    unsigned long long r;
    asm("mov.b64 %0, {%1, %1};" : "=l"(r) : "f"(v));
    return r;
}
__device__ __forceinline__ void fma2(unsigned long long& d, unsigned long long a,
                                     unsigned long long b) {
    asm("fma.rn.f32x2 %0, %1, %2, %0;" : "+l"(d) : "l"(a), "l"(b));
}
__device__ __forceinline__ unsigned long long add2(unsigned long long a,
                                                   unsigned long long b) {
    unsigned long long r;
    asm("add.rn.f32x2 %0, %1, %2;" : "=l"(r) : "l"(a), "l"(b));
    return r;
}
__device__ __forceinline__ void unpack2(float& lo, float& hi, unsigned long long v) {
    asm("mov.b64 {%0, %1}, %2;" : "=f"(lo), "=f"(hi) : "l"(v));
}
__device__ __forceinline__ float sqrt_ap(float v) {
    float r;
    asm("sqrt.approx.f32 %0, %1;" : "=f"(r) : "f"(v));
    return r;
}

// ---------- kernel 1: window squared norms + output init (fused) ----------
__global__ void winsq_kernel(const float* __restrict__ x, float* __restrict__ out) {
    int b = blockIdx.x, c = blockIdx.y;
    __shared__ float xs[LL];
    const float* xp = x + (b * CC + c) * LL;
    for (int i = threadIdx.x; i < LL; i += blockDim.x) xs[i] = xp[i];
    if (c == 0)
        out[b * 256 + threadIdx.x] = __int_as_float(0x7f800000);
    __syncthreads();
    for (int w = threadIdx.x; w < WPAD; w += blockDim.x) {
        float s = 0.f;
        if (w < WW) {
#pragma unroll 16
            for (int k = 0; k < SS; k++) { float v = xs[w + k]; s = fmaf(v, v, s); }
        }
        g_winsq[(b * CC + c) * WPAD + w] = s;
    }
}

// ---------- kernel 2: main ----------
__global__ __launch_bounds__(THREADS, 3) void main_kernel(
    const float* __restrict__ x, const float* __restrict__ shp,
    float* __restrict__ out)
{
    extern __shared__ __align__(16) unsigned char smem_raw[];
    float2* xd   = (float2*)smem_raw;                        // CC*XS pairs (7680 B)
    float2* shs2 = xd + CC * XS;                             // CC*NPAIR*66 (25344 B)
    float*  wss  = (float*)(shs2 + CC * NPAIR * SHP_STRIDE); // CC*WPB (3072 B)
    float2* sqs2 = (float2*)(wss + CC * WPB);                // CC*NPAIR (384 B)
    __shared__ float red[8][NPAIR][2];

    const int ntile = blockIdx.x;      // 0..7
    const int b     = blockIdx.y;      // 0..63
    const int wsl   = blockIdx.z;      // 0..7
    const int tid   = threadIdx.x;
    const int npair = tid & (NPAIR - 1);
    const int wg    = tid >> 4;        // 0..15
    const int warp  = tid >> 5;
    const int lane  = tid & 31;
    const int wbase = wsl * WPB;

    // Stage x window as duplicated pairs (clamped)
    for (int i = tid; i < CC * XS; i += THREADS) {
        int c = i / XS, j = i - c * XS;
        float v = x[(b * CC + c) * LL + min(wbase + j, LL - 1)];
        xd[i] = make_float2(v, v);
    }
    // Stage shapelet tile, n-pair interleaved, 16B-aligned padded rows
    for (int i = tid; i < CC * NPAIR * SS; i += THREADS) {
        int c = i / (NPAIR * SS);
        int r = i - c * (NPAIR * SS);
        int p = r / SS, s = r - p * SS;
        int n0 = ntile * NT + 2 * p;
        float2 v;
        v.x = shp[(c * NN + n0) * SS + s];
        v.y = shp[(c * NN + n0 + 1) * SS + s];
        shs2[(c * NPAIR + p) * SHP_STRIDE + s] = v;
    }
    // Stage winsq slice
    for (int i = tid; i < CC * WPB; i += THREADS) {
        int c = i >> 8, j = i & 255;
        wss[i] = g_winsq[(b * CC + c) * WPAD + wbase + j];
    }
    __syncthreads();

    // Shapelet squared norms per pair
    if (tid < CC * NPAIR) {
        int c = tid / NPAIR, p = tid - c * NPAIR;
        float a0 = 0.f, a1 = 0.f;
#pragma unroll 8
        for (int s = 0; s < SS; s++) {
            float2 v = shs2[(c * NPAIR + p) * SHP_STRIDE + s];
            a0 = fmaf(v.x, v.x, a0);
            a1 = fmaf(v.y, v.y, a1);
        }
        sqs2[tid] = make_float2(a0, a1);
    }
    __syncthreads();

    unsigned long long sqn2[CC];
#pragma unroll
    for (int c = 0; c < CC; c++) {
        float2 q = sqs2[c * NPAIR + npair];
        unsigned long long r;
        asm("mov.b64 %0, {%1, %2};" : "=l"(r) : "f"(q.x), "f"(q.y));
        sqn2[c] = r;
    }
    const unsigned long long NEG2 = pack2(-2.0f);
    const float INF = __int_as_float(0x7f800000);
    float tmin0 = INF, tmin1 = INF;

#pragma unroll
    for (int chunk = 0; chunk < CHUNKS; chunk++) {
        const int w0l = chunk * (WG * WPT) + wg * WPT;   // local w, even

        float t0[WPT], t1[WPT];
#pragma unroll
        for (int j = 0; j < WPT; j++) { t0[j] = 0.f; t1[j] = 0.f; }

#pragma unroll
        for (int c = 0; c < CC; c++) {
            const unsigned long long* xr =
                (const unsigned long long*)(xd + c * XS + w0l);
            const unsigned long long* shrow =
                (const unsigned long long*)(shs2 + (c * NPAIR + npair) * SHP_STRIDE);

            unsigned long long acc2[WPT];
#pragma unroll
            for (int j = 0; j < WPT; j++) acc2[j] = 0ull;

            // rolling packed window of 8 duplicated x pairs (vector-filled)
            unsigned long long xw2[8];
#pragma unroll
            for (int k = 0; k < 4; k++) {
                ulonglong2 v = ((const ulonglong2*)xr)[k];
                xw2[2 * k] = v.x;
                xw2[2 * k + 1] = v.y;
            }

            for (int sb = 0; sb < SS; sb += 8) {
#pragma unroll
                for (int up = 0; up < 4; up++) {
                    const int u = 2 * up;
                    const int s = sb + u;
                    // one 128b load = two shapelet steps; one = two x refills
                    ulonglong2 sh2p = *(const ulonglong2*)(shrow + s);
                    ulonglong2 xnp  = *(const ulonglong2*)(xr + s + 8);
#pragma unroll
                    for (int j = 0; j < WPT; j++)
                        fma2(acc2[j], xw2[(u + j) & 7], sh2p.x);
                    xw2[u] = xnp.x;
#pragma unroll
                    for (int j = 0; j < WPT; j++)
                        fma2(acc2[j], xw2[(u + 1 + j) & 7], sh2p.y);
                    xw2[u + 1] = xnp.y;
                }
            }

            // epilogue: d2 = ws + sqn - 2*cross
            const float4* wsv4 = (const float4*)(wss + c * WPB + w0l);
            float4 wa = wsv4[0], wb = wsv4[1];
            float wsv[8] = {wa.x, wa.y, wa.z, wa.w, wb.x, wb.y, wb.z, wb.w};
#pragma unroll
            for (int j = 0; j < WPT; j++) {
                unsigned long long base = add2(pack2(wsv[j]), sqn2[c]);
                fma2(base, acc2[j], NEG2);
                float lo, hi;
                unpack2(lo, hi, base);
                t0[j] += sqrt_ap(fmaxf(lo, 0.f));
                t1[j] += sqrt_ap(fmaxf(hi, 0.f));
            }
        }

#pragma unroll
        for (int j = 0; j < WPT; j++) {
            if (wbase + w0l + j < WW) {
                tmin0 = fminf(tmin0, t0[j]);
                tmin1 = fminf(tmin1, t1[j]);
            }
        }
    }

    // reduce across 16 w-groups: lane bit 4, then cross-warp via smem
    tmin0 = fminf(tmin0, __shfl_xor_sync(0xffffffffu, tmin0, 16));
    tmin1 = fminf(tmin1, __shfl_xor_sync(0xffffffffu, tmin1, 16));
    if (lane < NPAIR) {
        red[warp][lane][0] = tmin0;
        red[warp][lane][1] = tmin1;
    }
    __syncthreads();
    if (tid < NPAIR) {
        float m0 = red[0][tid][0], m1 = red[0][tid][1];
#pragma unroll
        for (int wr = 1; wr < 8; wr++) {
            m0 = fminf(m0, red[wr][tid][0]);
            m1 = fminf(m1, red[wr][tid][1]);
        }
        unsigned int* ob = (unsigned int*)(out + b * NN + ntile * NT + 2 * tid);
        atomicMin(ob,     __float_as_uint(m0));
        atomicMin(ob + 1, __float_as_uint(m1));
    }
}

extern "C" void kernel_launch(void* const* d_in, const int* in_sizes, int n_in,
                              void* d_out, int out_size) {
    (void)in_sizes; (void)n_in; (void)out_size;
    const float* x   = (const float*)d_in[0];
    const float* shp = (const float*)d_in[1];
    float* out = (float*)d_out;

    const int smem_bytes = CC * XS * 8 + CC * NPAIR * SHP_STRIDE * 8 + CC * WPB * 4 + CC * NPAIR * 8;
    cudaFuncSetAttribute(main_kernel, cudaFuncAttributeMaxDynamicSharedMemorySize, smem_bytes);

    winsq_kernel<<<dim3(BB, CC), 256>>>(x, out);
    main_kernel<<<dim3(NN / NT, BB, WSLICE), THREADS, smem_bytes>>>(x, shp, out);
}

// round 6
// speedup vs baseline: 2.9399x; 2.9399x over previous
#include <cuda_runtime.h>
#include <math.h>
#include <stdint.h>

#define SS 64
#define NN 256
#define CC 3
#define BB 64
#define LL 2048
#define WW (LL - SS + 1)   /* 1985 */
#define WPAD 2048
#define NT 32              /* shapelets per block */
#define NPAIR 16
#define WG 16              /* w-groups (threads dim) */
#define WPT 8              /* w per thread per chunk */
#define WSLICE 8           /* w slices (blockIdx.z) */
#define WPB 256            /* w per block */
#define CHUNKS 2           /* 2 x 128 w per block */
#define XS 320             /* staged x values per channel */
#define THREADS 256

__device__ float g_winsq[BB * CC * WPAD];

// ---------- packed f32x2 helpers (sm_103a fma pipe, 2x fp32 throughput) ----------
__device__ __forceinline__ unsigned long long pack2(float v) {
    unsigned long long r;
    asm("mov.b64 %0, {%1, %1};" : "=l"(r) : "f"(v));
    return r;
}
__device__ __forceinline__ void fma2(unsigned long long& d, unsigned long long a,
                                     unsigned long long b) {
    asm("fma.rn.f32x2 %0, %1, %2, %0;" : "+l"(d) : "l"(a), "l"(b));
}
__device__ __forceinline__ unsigned long long add2(unsigned long long a,
                                                   unsigned long long b) {
    unsigned long long r;
    asm("add.rn.f32x2 %0, %1, %2;" : "=l"(r) : "l"(a), "l"(b));
    return r;
}
__device__ __forceinline__ void unpack2(float& lo, float& hi, unsigned long long v) {
    asm("mov.b64 {%0, %1}, %2;" : "=f"(lo), "=f"(hi) : "l"(v));
}
__device__ __forceinline__ float sqrt_ap(float v) {
    float r;
    asm("sqrt.approx.f32 %0, %1;" : "=f"(r) : "f"(v));
    return r;
}

// ---------- kernel 1: window squared norms + output init (fused) ----------
__global__ void winsq_kernel(const float* __restrict__ x, float* __restrict__ out) {
    int b = blockIdx.x, c = blockIdx.y;
    __shared__ float xs[LL];
    const float* xp = x + (b * CC + c) * LL;
    for (int i = threadIdx.x; i < LL; i += blockDim.x) xs[i] = xp[i];
    if (c == 0)
        out[b * 256 + threadIdx.x] = __int_as_float(0x7f800000);
    __syncthreads();
    for (int w = threadIdx.x; w < WPAD; w += blockDim.x) {
        float s = 0.f;
        if (w < WW) {
#pragma unroll 16
            for (int k = 0; k < SS; k++) { float v = xs[w + k]; s = fmaf(v, v, s); }
        }
        g_winsq[(b * CC + c) * WPAD + w] = s;
    }
}

// ---------- kernel 2: main ----------
__global__ __launch_bounds__(THREADS, 3) void main_kernel(
    const float* __restrict__ x, const float* __restrict__ shp,
    float* __restrict__ out)
{
    extern __shared__ __align__(16) unsigned char smem_raw[];
    float2* xd   = (float2*)smem_raw;                 // CC*XS duplicated pairs (7680 B)
    float2* shs2 = xd + CC * XS;                      // CC*NPAIR*65 (24960 B)
    float2* wsd  = shs2 + CC * NPAIR * 65;            // CC*WPB duplicated pairs (6144 B)
    float2* sqs2 = wsd + CC * WPB;                    // CC*NPAIR (384 B)
    __shared__ float red[8][NPAIR][2];

    const int ntile = blockIdx.x;      // 0..7
    const int b     = blockIdx.y;      // 0..63
    const int wsl   = blockIdx.z;      // 0..7
    const int tid   = threadIdx.x;
    const int npair = tid & (NPAIR - 1);
    const int wg    = tid >> 4;        // 0..15
    const int warp  = tid >> 5;
    const int lane  = tid & 31;
    const int wbase = wsl * WPB;

    // Stage x window as duplicated pairs (clamped)
    for (int i = tid; i < CC * XS; i += THREADS) {
        int c = i / XS, j = i - c * XS;
        float v = x[(b * CC + c) * LL + min(wbase + j, LL - 1)];
        xd[i] = make_float2(v, v);
    }
    // Stage shapelet tile, n-pair interleaved, pad 65
    for (int i = tid; i < CC * NPAIR * SS; i += THREADS) {
        int c = i / (NPAIR * SS);
        int r = i - c * (NPAIR * SS);
        int p = r / SS, s = r - p * SS;
        int n0 = ntile * NT + 2 * p;
        float2 v;
        v.x = shp[(c * NN + n0) * SS + s];
        v.y = shp[(c * NN + n0 + 1) * SS + s];
        shs2[(c * NPAIR + p) * 65 + s] = v;
    }
    // Stage winsq slice as duplicated pairs
    for (int i = tid; i < CC * WPB; i += THREADS) {
        int c = i >> 8, j = i & 255;
        float v = g_winsq[(b * CC + c) * WPAD + wbase + j];
        wsd[i] = make_float2(v, v);
    }
    __syncthreads();

    // Shapelet squared norms per pair
    if (tid < CC * NPAIR) {
        int c = tid / NPAIR, p = tid - c * NPAIR;
        float a0 = 0.f, a1 = 0.f;
#pragma unroll 8
        for (int s = 0; s < SS; s++) {
            float2 v = shs2[(c * NPAIR + p) * 65 + s];
            a0 = fmaf(v.x, v.x, a0);
            a1 = fmaf(v.y, v.y, a1);
        }
        sqs2[tid] = make_float2(a0, a1);
    }
    __syncthreads();

    unsigned long long sqn2[CC];
#pragma unroll
    for (int c = 0; c < CC; c++) {
        float2 q = sqs2[c * NPAIR + npair];
        unsigned long long r;
        asm("mov.b64 %0, {%1, %2};" : "=l"(r) : "f"(q.x), "f"(q.y));
        sqn2[c] = r;
    }
    const unsigned long long NEG2 = pack2(-2.0f);
    const float INF = __int_as_float(0x7f800000);
    float tmin0 = INF, tmin1 = INF;

#pragma unroll
    for (int chunk = 0; chunk < CHUNKS; chunk++) {
        const int w0l = chunk * (WG * WPT) + wg * WPT;   // local w, 0..248

        float t0[WPT], t1[WPT];
#pragma unroll
        for (int j = 0; j < WPT; j++) { t0[j] = 0.f; t1[j] = 0.f; }

#pragma unroll
        for (int c = 0; c < CC; c++) {
            const unsigned long long* xr =
                (const unsigned long long*)(xd + c * XS + w0l);
            const unsigned long long* shrow =
                (const unsigned long long*)(shs2 + (c * NPAIR + npair) * 65);

            unsigned long long acc2[WPT];
#pragma unroll
            for (int j = 0; j < WPT; j++) acc2[j] = 0ull;

            // rolling packed window of 8 duplicated x pairs
            unsigned long long xw2[8];
#pragma unroll
            for (int k = 0; k < 8; k++) xw2[k] = xr[k];

            for (int sb = 0; sb < SS; sb += 8) {
#pragma unroll
                for (int u = 0; u < 8; u++) {
                    int s = sb + u;
                    unsigned long long sh2 = shrow[s];
#pragma unroll
                    for (int j = 0; j < WPT; j++)
                        fma2(acc2[j], xw2[(u + j) & 7], sh2);
                    xw2[u] = xr[s + 8];   // max index w0l+71 <= 319
                }
            }

            // epilogue: d2 = ws + sqn - 2*cross (ws already duplicated in smem)
            const unsigned long long* wsrow =
                (const unsigned long long*)(wsd + c * WPB + w0l);
#pragma unroll
            for (int j = 0; j < WPT; j++) {
                unsigned long long base = add2(wsrow[j], sqn2[c]);
                fma2(base, acc2[j], NEG2);
                float lo, hi;
                unpack2(lo, hi, base);
                t0[j] += sqrt_ap(fmaxf(lo, 0.f));
                t1[j] += sqrt_ap(fmaxf(hi, 0.f));
            }
        }

#pragma unroll
        for (int j = 0; j < WPT; j++) {
            if (wbase + w0l + j < WW) {
                tmin0 = fminf(tmin0, t0[j]);
                tmin1 = fminf(tmin1, t1[j]);
            }
        }
    }

    // reduce across 16 w-groups: lane bit 4, then cross-warp via smem
    tmin0 = fminf(tmin0, __shfl_xor_sync(0xffffffffu, tmin0, 16));
    tmin1 = fminf(tmin1, __shfl_xor_sync(0xffffffffu, tmin1, 16));
    if (lane < NPAIR) {
        red[warp][lane][0] = tmin0;
        red[warp][lane][1] = tmin1;
    }
    __syncthreads();
    if (tid < NPAIR) {
        float m0 = red[0][tid][0], m1 = red[0][tid][1];
#pragma unroll
        for (int wr = 1; wr < 8; wr++) {
            m0 = fminf(m0, red[wr][tid][0]);
            m1 = fminf(m1, red[wr][tid][1]);
        }
        unsigned int* ob = (unsigned int*)(out + b * NN + ntile * NT + 2 * tid);
        atomicMin(ob,     __float_as_uint(m0));
        atomicMin(ob + 1, __float_as_uint(m1));
    }
}

extern "C" void kernel_launch(void* const* d_in, const int* in_sizes, int n_in,
                              void* d_out, int out_size) {
    (void)in_sizes; (void)n_in; (void)out_size;
    const float* x   = (const float*)d_in[0];
    const float* shp = (const float*)d_in[1];
    float* out = (float*)d_out;

    const int smem_bytes = CC * XS * 8 + CC * NPAIR * 65 * 8 + CC * WPB * 8 + CC * NPAIR * 8;
    cudaFuncSetAttribute(main_kernel, cudaFuncAttributeMaxDynamicSharedMemorySize, smem_bytes);

    winsq_kernel<<<dim3(BB, CC), 256>>>(x, out);
    main_kernel<<<dim3(NN / NT, BB, WSLICE), THREADS, smem_bytes>>>(x, shp, out);
}